// round 9
// baseline (speedup 1.0000x reference)
#include <cuda_runtime.h>
#include <cstdint>

// Problem constants (fixed by the dataset)
#define NMAX 100000
#define EMAX 800000
#define C 96            // IN_C
#define OC 64           // OUT_C
#define SCAN_B 1024
#define NB_MAX 128      // ceil(NMAX/1024) = 98

// ---- scratch (static device globals; no allocation at runtime) ----
// NOTE: these symbols are ONLY referenced from device code. Passing them as
// kernel args from host passes the host shadow address (ATS makes it "work"
// but reads host memory) — that was the R3-R7 bug.
__device__ int   g_ecount[NMAX];      // in-degree over real edges (excl. self loop)
__device__ int   g_cursor[NMAX];
__device__ int   g_csr_start[NMAX];
__device__ int   g_bsums[NB_MAX];
__device__ float g_dinv[NMAX];
__device__ int   g_csr_src[EMAX];
__device__ float g_z[(size_t)NMAX * OC];    // x @ W^T
__device__ float g_h[(size_t)NMAX * OC];    // after hop 1

// ---------------------------------------------------------------- init
__global__ void k_init(int n) {
    int i = blockIdx.x * blockDim.x + threadIdx.x;
    if (i < n) { g_ecount[i] = 0; g_cursor[i] = 0; }
}

// ---------------------------------------------------------------- histogram over col
// edge_index arrives as int32 (JAX x64 disabled downcasts int64 -> int32)
__global__ void k_hist(const int* __restrict__ ei, int e) {
    int i = blockIdx.x * blockDim.x + threadIdx.x;
    if (i < e) {
        int col = ei[e + i];
        atomicAdd(&g_ecount[col], 1);
    }
}

// ---------------------------------------------------------------- block-level exclusive scan
__global__ void k_scan_blocks(int n) {
    __shared__ int s[SCAN_B];
    int tid = threadIdx.x;
    int i = blockIdx.x * SCAN_B + tid;
    int v = (i < n) ? g_ecount[i] : 0;
    s[tid] = v;
    __syncthreads();
    for (int off = 1; off < SCAN_B; off <<= 1) {
        int t = (tid >= off) ? s[tid - off] : 0;
        __syncthreads();
        s[tid] += t;
        __syncthreads();
    }
    if (i < n) g_csr_start[i] = s[tid] - v;   // exclusive
    if (tid == SCAN_B - 1) g_bsums[blockIdx.x] = s[SCAN_B - 1];
}

// parallel exclusive scan over the (<=128) block sums; single block of 128
__global__ void k_scan_sums(int nb) {
    __shared__ int s[128];
    int t = threadIdx.x;
    int v = (t < nb) ? g_bsums[t] : 0;
    s[t] = v;
    __syncthreads();
    for (int off = 1; off < 128; off <<= 1) {
        int u = (t >= off) ? s[t - off] : 0;
        __syncthreads();
        s[t] += u;
        __syncthreads();
    }
    if (t < nb) g_bsums[t] = s[t] - v;   // exclusive
}

__global__ void k_scan_fixup(int n) {
    int i = blockIdx.x * blockDim.x + threadIdx.x;
    if (i < n) {
        g_csr_start[i] += g_bsums[i >> 10];
        g_dinv[i] = rsqrtf((float)(g_ecount[i] + 1));   // deg includes self loop
    }
}

// ---------------------------------------------------------------- CSR fill (by destination)
__global__ void k_fill(const int* __restrict__ ei, int e) {
    int i = blockIdx.x * blockDim.x + threadIdx.x;
    if (i < e) {
        int src = ei[i];
        int col = ei[e + i];
        int pos = g_csr_start[col] + atomicAdd(&g_cursor[col], 1);
        g_csr_src[pos] = src;
    }
}

// ---------------------------------------------------------------- GEMM: z = x @ W^T  (N x 96 @ 96 x 64)
// block tile: 32 nodes x 64 oc, 256 threads
// thread (tx = t%16, ty = t/16): oc in {tx, tx+16, tx+32, tx+48}, nodes {ty*2, ty*2+1}
__global__ void k_gemm(const float* __restrict__ x, const float* __restrict__ Wm, int n) {
    __shared__ float ws[OC][C + 1];       // pad 97 -> conflict-free strided-oc reads
    __shared__ float xs[C][34];           // transposed x tile, pad 34 keeps float2 aligned

    int t = threadIdx.x;
    int node0 = blockIdx.x * 32;

    for (int i = t; i < OC * C; i += 256) {
        ws[i / C][i % C] = Wm[i];
    }
    for (int i = t; i < 32 * C; i += 256) {
        int nl = i / C, ic = i % C;
        int node = node0 + nl;
        xs[ic][nl] = (node < n) ? x[(size_t)node * C + ic] : 0.0f;
    }
    __syncthreads();

    int tx = t & 15;
    int ty = t >> 4;

    float acc[2][4];
#pragma unroll
    for (int i = 0; i < 2; i++)
#pragma unroll
        for (int j = 0; j < 4; j++) acc[i][j] = 0.0f;

#pragma unroll 4
    for (int ic = 0; ic < C; ic++) {
        float2 xv = *(const float2*)&xs[ic][ty * 2];
        float w0 = ws[tx][ic];
        float w1 = ws[tx + 16][ic];
        float w2 = ws[tx + 32][ic];
        float w3 = ws[tx + 48][ic];
        acc[0][0] += xv.x * w0;  acc[1][0] += xv.y * w0;
        acc[0][1] += xv.x * w1;  acc[1][1] += xv.y * w1;
        acc[0][2] += xv.x * w2;  acc[1][2] += xv.y * w2;
        acc[0][3] += xv.x * w3;  acc[1][3] += xv.y * w3;
    }

#pragma unroll
    for (int i = 0; i < 2; i++) {
        int node = node0 + ty * 2 + i;
        if (node < n) {
#pragma unroll
            for (int j = 0; j < 4; j++) {
                g_z[(size_t)node * OC + tx + j * 16] = acc[i][j];
            }
        }
    }
}

// ---------------------------------------------------------------- propagation hop on 64 channels
// y[c] = dinv[c]^2 * z[c] + sum_{s in N_in(c)} dinv[s]*dinv[c]*z[s]
// one warp per destination node; lane covers channels {2*lane, 2*lane+1} via float2
// PASS 0: g_z -> g_h ; PASS 1: g_h -> out (+ bias + sigmoid)
// Buffer selection happens IN DEVICE CODE (device-global symbols must not
// cross the host/device boundary as kernel args).
template <int PASS>
__global__ void k_hop64(float* __restrict__ out, const float* __restrict__ bias, int n) {
    const float* __restrict__ xin = (PASS == 0) ? g_z : g_h;

    int warp = (blockIdx.x * blockDim.x + threadIdx.x) >> 5;
    int lane = threadIdx.x & 31;
    if (warp >= n) return;

    int c = warp;
    float dc = g_dinv[c];
    float2 v = ((const float2*)(xin + (size_t)c * OC))[lane];
    float wl = dc * dc;
    float a0 = wl * v.x;
    float a1 = wl * v.y;

    int st  = g_csr_start[c];
    int cnt = g_ecount[c];
    const int* __restrict__ srcs = g_csr_src + st;

    int k = 0;
    // 4-way unrolled: batch independent index+dinv+row gathers for MLP
    for (; k + 4 <= cnt; k += 4) {
        int s0 = srcs[k + 0];
        int s1 = srcs[k + 1];
        int s2 = srcs[k + 2];
        int s3 = srcs[k + 3];
        float w0 = dc * g_dinv[s0];
        float w1 = dc * g_dinv[s1];
        float w2 = dc * g_dinv[s2];
        float w3 = dc * g_dinv[s3];
        float2 v0 = ((const float2*)(xin + (size_t)s0 * OC))[lane];
        float2 v1 = ((const float2*)(xin + (size_t)s1 * OC))[lane];
        float2 v2 = ((const float2*)(xin + (size_t)s2 * OC))[lane];
        float2 v3 = ((const float2*)(xin + (size_t)s3 * OC))[lane];
        a0 += w0 * v0.x;  a1 += w0 * v0.y;
        a0 += w1 * v1.x;  a1 += w1 * v1.y;
        a0 += w2 * v2.x;  a1 += w2 * v2.y;
        a0 += w3 * v3.x;  a1 += w3 * v3.y;
    }
    for (; k < cnt; k++) {
        int s   = srcs[k];
        float w = dc * g_dinv[s];
        float2 xv = ((const float2*)(xin + (size_t)s * OC))[lane];
        a0 += w * xv.x;
        a1 += w * xv.y;
    }

    if (PASS == 1) {
        float b0 = bias[2 * lane];
        float b1 = bias[2 * lane + 1];
        float2 r;
        r.x = 1.0f / (1.0f + __expf(-(a0 + b0)));
        r.y = 1.0f / (1.0f + __expf(-(a1 + b1)));
        ((float2*)(out + (size_t)c * OC))[lane] = r;
    } else {
        float2 r; r.x = a0; r.y = a1;
        ((float2*)(g_h + (size_t)c * OC))[lane] = r;
    }
}

// ---------------------------------------------------------------- launch
extern "C" void kernel_launch(void* const* d_in, const int* in_sizes, int n_in,
                              void* d_out, int out_size) {
    const float* x  = (const float*)d_in[0];
    const int*   ei = (const int*)d_in[1];
    const float* Wm = (const float*)d_in[2];
    const float* b  = (const float*)d_in[3];
    float* out = (float*)d_out;

    int n = in_sizes[0] / C;   // 100000
    int e = in_sizes[1] / 2;   // 800000
    int nb = (n + SCAN_B - 1) / SCAN_B;

    // CSR build
    k_init<<<(n + 255) / 256, 256>>>(n);
    k_hist<<<(e + 255) / 256, 256>>>(ei, e);
    k_scan_blocks<<<nb, SCAN_B>>>(n);
    k_scan_sums<<<1, 128>>>(nb);
    k_scan_fixup<<<(n + 255) / 256, 256>>>(n);
    k_fill<<<(e + 255) / 256, 256>>>(ei, e);

    // z = x @ W^T  (apply linear FIRST; propagation commutes with per-node linear map)
    k_gemm<<<(n + 31) / 32, 256>>>(x, Wm, n);

    // two hops on 64 channels; final hop fuses bias + sigmoid
    int hop_blocks = (n + 15) / 16;   // 16 warps (nodes) per 512-thread block
    k_hop64<0><<<hop_blocks, 512>>>(nullptr, nullptr, n);
    k_hop64<1><<<hop_blocks, 512>>>(out, b, n);
}

// round 10
// speedup vs baseline: 1.5159x; 1.5159x over previous
#include <cuda_runtime.h>
#include <cstdint>

// Problem constants (fixed by the dataset)
#define NMAX 100000
#define EMAX 800000
#define C 96            // IN_C
#define OC 64           // OUT_C
#define SCAN_B 1024
#define NB_MAX 128      // ceil(NMAX/1024) = 98

// ---- scratch (static device globals; no allocation at runtime) ----
// These symbols are ONLY referenced from device code. Passing them as kernel
// args from host passes the host shadow address (ATS silently reads host
// memory) — that was the R3-R7 bug.
__device__ int   g_ecount[NMAX];      // in-degree over real edges (excl. self loop)
__device__ int   g_cursor[NMAX];
__device__ int   g_csr_start[NMAX];
__device__ int   g_bsums[NB_MAX];
__device__ float g_dinv[NMAX];
__device__ int   g_csr_src[EMAX];
__device__ float g_z[(size_t)NMAX * OC];    // x @ W^T
__device__ float g_h[(size_t)NMAX * OC];    // after hop 1

// ---------------------------------------------------------------- init
__global__ void k_init(int n) {
    int i = blockIdx.x * blockDim.x + threadIdx.x;
    if (i < n) { g_ecount[i] = 0; g_cursor[i] = 0; }
}

// ---------------------------------------------------------------- histogram over col
// edge_index arrives as int32 (JAX x64 disabled downcasts int64 -> int32)
__global__ void k_hist(const int* __restrict__ ei, int e) {
    int i = blockIdx.x * blockDim.x + threadIdx.x;
    if (i < e) {
        int col = ei[e + i];
        atomicAdd(&g_ecount[col], 1);
    }
}

// ---------------------------------------------------------------- block-level exclusive scan
__global__ void k_scan_blocks(int n) {
    __shared__ int s[SCAN_B];
    int tid = threadIdx.x;
    int i = blockIdx.x * SCAN_B + tid;
    int v = (i < n) ? g_ecount[i] : 0;
    s[tid] = v;
    __syncthreads();
    for (int off = 1; off < SCAN_B; off <<= 1) {
        int t = (tid >= off) ? s[tid - off] : 0;
        __syncthreads();
        s[tid] += t;
        __syncthreads();
    }
    if (i < n) g_csr_start[i] = s[tid] - v;   // exclusive
    if (tid == SCAN_B - 1) g_bsums[blockIdx.x] = s[SCAN_B - 1];
}

// parallel exclusive scan over the (<=128) block sums; single block of 128
__global__ void k_scan_sums(int nb) {
    __shared__ int s[128];
    int t = threadIdx.x;
    int v = (t < nb) ? g_bsums[t] : 0;
    s[t] = v;
    __syncthreads();
    for (int off = 1; off < 128; off <<= 1) {
        int u = (t >= off) ? s[t - off] : 0;
        __syncthreads();
        s[t] += u;
        __syncthreads();
    }
    if (t < nb) g_bsums[t] = s[t] - v;   // exclusive
}

__global__ void k_scan_fixup(int n) {
    int i = blockIdx.x * blockDim.x + threadIdx.x;
    if (i < n) {
        g_csr_start[i] += g_bsums[i >> 10];
        g_dinv[i] = rsqrtf((float)(g_ecount[i] + 1));   // deg includes self loop
    }
}

// ---------------------------------------------------------------- CSR fill (by destination)
__global__ void k_fill(const int* __restrict__ ei, int e) {
    int i = blockIdx.x * blockDim.x + threadIdx.x;
    if (i < e) {
        int src = ei[i];
        int col = ei[e + i];
        int pos = g_csr_start[col] + atomicAdd(&g_cursor[col], 1);
        g_csr_src[pos] = src;
    }
}

// ---------------------------------------------------------------- GEMM: z = x @ W^T  (N x 96 @ 96 x 64)
// block tile: 32 nodes x 64 oc, 256 threads
// thread (tx = t%16, ty = t/16): oc in {tx, tx+16, tx+32, tx+48}, nodes {ty*2, ty*2+1}
__global__ void k_gemm(const float* __restrict__ x, const float* __restrict__ Wm, int n) {
    __shared__ float ws[OC][C + 1];       // pad 97 -> conflict-free strided-oc reads
    __shared__ float xs[C][34];           // transposed x tile, pad 34 keeps float2 aligned

    int t = threadIdx.x;
    int node0 = blockIdx.x * 32;

    for (int i = t; i < OC * C; i += 256) {
        ws[i / C][i % C] = Wm[i];
    }
    for (int i = t; i < 32 * C; i += 256) {
        int nl = i / C, ic = i % C;
        int node = node0 + nl;
        xs[ic][nl] = (node < n) ? x[(size_t)node * C + ic] : 0.0f;
    }
    __syncthreads();

    int tx = t & 15;
    int ty = t >> 4;

    float acc[2][4];
#pragma unroll
    for (int i = 0; i < 2; i++)
#pragma unroll
        for (int j = 0; j < 4; j++) acc[i][j] = 0.0f;

#pragma unroll 4
    for (int ic = 0; ic < C; ic++) {
        float2 xv = *(const float2*)&xs[ic][ty * 2];
        float w0 = ws[tx][ic];
        float w1 = ws[tx + 16][ic];
        float w2 = ws[tx + 32][ic];
        float w3 = ws[tx + 48][ic];
        acc[0][0] += xv.x * w0;  acc[1][0] += xv.y * w0;
        acc[0][1] += xv.x * w1;  acc[1][1] += xv.y * w1;
        acc[0][2] += xv.x * w2;  acc[1][2] += xv.y * w2;
        acc[0][3] += xv.x * w3;  acc[1][3] += xv.y * w3;
    }

#pragma unroll
    for (int i = 0; i < 2; i++) {
        int node = node0 + ty * 2 + i;
        if (node < n) {
#pragma unroll
            for (int j = 0; j < 4; j++) {
                g_z[(size_t)node * OC + tx + j * 16] = acc[i][j];
            }
        }
    }
}

// ---------------------------------------------------------------- propagation hop on 64 channels
// y[c] = dinv[c]^2 * z[c] + sum_{s in N_in(c)} dinv[s]*dinv[c]*z[s]
// one warp per destination node; lane covers channels {2*lane, 2*lane+1} via float2
// SIMPLE serial edge loop (MLP_p1 = 1): the R8 4-way unroll front-batched the
// gathers and triggered cross-CTA L1tex-queue contention (spr_max ~2x) per the
// B300 multi-CTA spread model. Serial loop keeps the spread at the ~1.1 floor.
// PASS 0: g_z -> g_h ; PASS 1: g_h -> out (+ bias + sigmoid)
template <int PASS>
__global__ void k_hop64(float* __restrict__ out, const float* __restrict__ bias, int n) {
    const float* __restrict__ xin = (PASS == 0) ? g_z : g_h;

    int warp = (blockIdx.x * blockDim.x + threadIdx.x) >> 5;
    int lane = threadIdx.x & 31;
    if (warp >= n) return;

    int c = warp;
    float dc = g_dinv[c];
    float2 v = ((const float2*)(xin + (size_t)c * OC))[lane];
    float wl = dc * dc;
    float a0 = wl * v.x;
    float a1 = wl * v.y;

    int st  = g_csr_start[c];
    int cnt = g_ecount[c];
    const int* __restrict__ srcs = g_csr_src + st;
    for (int k = 0; k < cnt; k++) {
        int s   = srcs[k];
        float w = dc * g_dinv[s];
        float2 xv = ((const float2*)(xin + (size_t)s * OC))[lane];
        a0 += w * xv.x;
        a1 += w * xv.y;
    }

    if (PASS == 1) {
        float b0 = bias[2 * lane];
        float b1 = bias[2 * lane + 1];
        float2 r;
        r.x = 1.0f / (1.0f + __expf(-(a0 + b0)));
        r.y = 1.0f / (1.0f + __expf(-(a1 + b1)));
        ((float2*)(out + (size_t)c * OC))[lane] = r;
    } else {
        float2 r; r.x = a0; r.y = a1;
        ((float2*)(g_h + (size_t)c * OC))[lane] = r;
    }
}

// ---------------------------------------------------------------- launch
extern "C" void kernel_launch(void* const* d_in, const int* in_sizes, int n_in,
                              void* d_out, int out_size) {
    const float* x  = (const float*)d_in[0];
    const int*   ei = (const int*)d_in[1];
    const float* Wm = (const float*)d_in[2];
    const float* b  = (const float*)d_in[3];
    float* out = (float*)d_out;

    int n = in_sizes[0] / C;   // 100000
    int e = in_sizes[1] / 2;   // 800000
    int nb = (n + SCAN_B - 1) / SCAN_B;

    // CSR build
    k_init<<<(n + 255) / 256, 256>>>(n);
    k_hist<<<(e + 255) / 256, 256>>>(ei, e);
    k_scan_blocks<<<nb, SCAN_B>>>(n);
    k_scan_sums<<<1, 128>>>(nb);
    k_scan_fixup<<<(n + 255) / 256, 256>>>(n);
    k_fill<<<(e + 255) / 256, 256>>>(ei, e);

    // z = x @ W^T  (apply linear FIRST; propagation commutes with per-node linear map)
    k_gemm<<<(n + 31) / 32, 256>>>(x, Wm, n);

    // two hops on 64 channels; final hop fuses bias + sigmoid
    int hop_blocks = (n + 7) / 8;     // 8 warps (nodes) per 256-thread block (R2-proven)
    k_hop64<0><<<hop_blocks, 256>>>(nullptr, nullptr, n);
    k_hop64<1><<<hop_blocks, 256>>>(out, b, n);
}